// round 14
// baseline (speedup 1.0000x reference)
#include <cuda_runtime.h>

#define NB     2048
#define NOH    20
#define NOTH   23
#define NC     10
#define SC     200      // NOH*NC
#define EMB    9
#define OUTC   32
#define XSTR   43       // NOH + NOTH
#define HW     2304     // 48*48
#define SLABSZ 73728    // OUTC*HW floats per batch

#define NCTA   512
#define TPB    256

// Device scratch + flags (zero-initialized; reset at end of every run)
__device__ float g_v[NB * EMB];
__device__ float g_slab[8 * SLABSZ];
__device__ int   g_vcount;
__device__ int   g_pcount[64 * 32];   // piece counters, padded 128B apart
__device__ int   g_done;

__device__ __forceinline__ int ld_vol(const int* p) {
    int v;
    asm volatile("ld.volatile.global.s32 %0, [%1];" : "=r"(v) : "l"(p));
    return v;
}

// Single kernel: v-rows -> slab pieces -> replicate, gated by device flags.
// All 512 CTAs are co-resident (<=64 regs, 256 thr, ~1KB smem => >=4 CTAs/SM,
// 592 slots), so spin-waits are deadlock-free.
//
// Verified identities (rel_err ~1.4e-7, R1-R13):
//   out[b][o][m] depends on b only through c = b & 7
//   three 1x1 convs fold into one 32x32 weight W + bias cb
//   slab[c][o][m] = cb[o] + sum_i W[o,i]  * v[256*((c+i)&7)+q, r]  (q=m/9, r=m%9)
//                         + sum_j W[o,9+j]* x[bb_j*43+20+(4j+m)%23],
//                           bb_j = (256c + (2304j+m)/23) & 2047
__global__ void __launch_bounds__(TPB, 4) k_all(
    const float* __restrict__ x,
    const float* __restrict__ fc_w, const float* __restrict__ fc_b,
    const float* __restrict__ oh_w, const float* __restrict__ oh_b,
    const float* __restrict__ ot_w, const float* __restrict__ ot_b,
    const float* __restrict__ all_w, const float* __restrict__ all_b,
    float* __restrict__ out)
{
    __shared__ __align__(16) float s_W[4 * 32];   // this piece's 4 channels
    __shared__ float s_cb[4];
    __shared__ bool s_last;

    const int t   = threadIdx.x;          // 0..255
    const int bid = blockIdx.x;           // 0..511
    const int p   = bid & 63;             // piece id
    const int bg  = bid >> 6;             // 0..7 batch group
    const int c   = p & 7;                // residue class
    const int ch  = p >> 3;               // 4-channel group 0..7
    const int o0  = ch * 4;

    // ================= phase 0: v rows [bid*4, bid*4+4) =====================
    // 36 work items: (row 0..3) x (e 0..8)
    if (t < 36) {
        int row = t / 9;
        int e   = t - row * 9;
        int b   = bid * 4 + row;
        const float* xr = x + b * XSTR;
        float acc = fc_b[e];
        #pragma unroll
        for (int j = 0; j < NOH; j++) {
            int id = (int)xr[j];
            acc += fc_w[e * SC + j * NC + id];
        }
        g_v[b * EMB + e] = acc;
    }

    // ---- fold this piece's 4 channels while v settles (128 entries) --------
    if (t < 128) {
        int o = o0 + (t >> 5);
        int i = t & 31;
        float s = 0.f;
        if (i < EMB) {
            #pragma unroll
            for (int cc = 0; cc < EMB; cc++)
                s += all_w[o * 32 + cc] * oh_w[cc * EMB + i];
        } else {
            int j = i - EMB;
            #pragma unroll
            for (int cc = 0; cc < NOTH; cc++)
                s += all_w[o * 32 + EMB + cc] * ot_w[cc * NOTH + j];
        }
        s_W[t] = s;
    }
    if (t < 4) {
        int o = o0 + t;
        float cb = all_b[o];
        #pragma unroll
        for (int cc = 0; cc < EMB; cc++)  cb += all_w[o * 32 + cc] * oh_b[cc];
        #pragma unroll
        for (int cc = 0; cc < NOTH; cc++) cb += all_w[o * 32 + EMB + cc] * ot_b[cc];
        s_cb[t] = cb;
    }

    __syncthreads();
    __threadfence();
    if (t == 0) atomicAdd(&g_vcount, 1);

    // ---- wait for all v rows ----------------------------------------------
    if (t == 0) {
        while (ld_vol(&g_vcount) < NCTA) __nanosleep(64);
    }
    __syncthreads();
    __threadfence();

    // ================= phase 1: slab piece slice ============================
    // piece p covers channels [o0,o0+4) x all m; this CTA does m in
    // [bg*288, bg*288+288). 288 m on 256 threads: t, and t+256 for t<32.
    {
        const int mbase = bg * 288;
        #pragma unroll
        for (int rep = 0; rep < 2; rep++) {
            int ml = t + rep * 256;
            if (rep == 1 && t >= 32) break;
            int m = mbase + ml;
            int q = m / 9;
            int r = m - 9 * q;

            float g[32];
            #pragma unroll
            for (int i = 0; i < 9; i++)
                g[i] = g_v[(256 * ((c + i) & 7) + q) * EMB + r];
            #pragma unroll
            for (int j = 0; j < 23; j++) {
                int eo = (4 * j + m) % 23;
                int T  = (2304 * j + m) / 23;
                int bb = (256 * c + T) & 2047;
                g[9 + j] = x[bb * XSTR + NOH + eo];
            }

            float* dst = g_slab + (size_t)c * SLABSZ + m;
            #pragma unroll
            for (int chn = 0; chn < 4; chn++) {
                const float4* W4 = (const float4*)(s_W + chn * 32);
                float s = s_cb[chn];
                #pragma unroll
                for (int j4 = 0; j4 < 8; j4++) {
                    float4 w = W4[j4];
                    s += w.x * g[4 * j4]     + w.y * g[4 * j4 + 1]
                       + w.z * g[4 * j4 + 2] + w.w * g[4 * j4 + 3];
                }
                dst[(size_t)(o0 + chn) * HW] = s;
            }
        }
    }

    __syncthreads();
    __threadfence();
    if (t == 0) atomicAdd(&g_pcount[p * 32], 1);

    // ---- wait until this piece is fully produced (8 arrivals) --------------
    if (t == 0) {
        while (ld_vol(&g_pcount[p * 32]) < 8) __nanosleep(64);
    }
    __syncthreads();
    __threadfence();

    // ================= phase 2: replicate ===================================
    // piece = 9216 floats = 36 KB contiguous at slab offset c*SLABSZ + ch*9216.
    // Stage 9 float4 per thread, store for 32 batches b = c + 8*(bg*32+u).
    const float4* __restrict__ src =
        (const float4*)(g_slab + (size_t)c * SLABSZ + (size_t)ch * 9216);

    float4 v0 = src[t];
    float4 v1 = src[t + 256];
    float4 v2 = src[t + 512];
    float4 v3 = src[t + 768];
    float4 v4 = src[t + 1024];
    float4 v5 = src[t + 1280];
    float4 v6 = src[t + 1536];
    float4 v7 = src[t + 1792];
    float4 v8 = src[t + 2048];

    float4* __restrict__ outb = (float4*)out
        + (size_t)c * (SLABSZ / 4) + (size_t)ch * 2304;

    #pragma unroll 4
    for (int u = 0; u < 32; u++) {
        int bb = bg * 32 + u;                 // b = c + 8*bb
        float4* __restrict__ dst = outb + (size_t)bb * (8 * SLABSZ / 4);
        dst[t]        = v0;
        dst[t + 256]  = v1;
        dst[t + 512]  = v2;
        dst[t + 768]  = v3;
        dst[t + 1024] = v4;
        dst[t + 1280] = v5;
        dst[t + 1536] = v6;
        dst[t + 1792] = v7;
        dst[t + 2048] = v8;
    }

    // ================= epilogue: last CTA resets flags ======================
    if (t == 0) {
        int d = atomicAdd(&g_done, 1);
        s_last = (d == NCTA - 1);
    }
    __syncthreads();
    if (s_last) {
        if (t == 0) g_vcount = 0;
        if (t < 64) g_pcount[t * 32] = 0;
        __syncthreads();
        if (t == 0) g_done = 0;
    }
}

// ---------------------------------------------------------------------------
extern "C" void kernel_launch(void* const* d_in, const int* in_sizes, int n_in,
                              void* d_out, int out_size) {
    const float* x     = (const float*)d_in[0];
    const float* fc_w  = (const float*)d_in[1];
    const float* fc_b  = (const float*)d_in[2];
    const float* oh_w  = (const float*)d_in[3];
    const float* oh_b  = (const float*)d_in[4];
    const float* ot_w  = (const float*)d_in[5];
    const float* ot_b  = (const float*)d_in[6];
    const float* all_w = (const float*)d_in[7];
    const float* all_b = (const float*)d_in[8];
    float* out = (float*)d_out;

    k_all<<<NCTA, TPB>>>(x, fc_w, fc_b, oh_w, oh_b, ot_w, ot_b,
                         all_w, all_b, out);
}

// round 15
// speedup vs baseline: 1.2205x; 1.2205x over previous
#include <cuda_runtime.h>

#define NB     2048
#define NOH    20
#define NOTH   23
#define NC     10
#define SC     200      // NOH*NC
#define EMB    9
#define OUTC   32
#define XSTR   43       // NOH + NOTH
#define HW     2304     // 48*48
#define SLABSZ 73728    // OUTC*HW floats per batch

#define THREADS 1024

// Single fused, single-wave kernel (R10 structure, proven 104.7us), with the
// one change: output stores are streaming (__stcs, evict-first) to smooth the
// 604MB L2 writeback drain across graph-replay boundaries.
//
// Verified identities (rel_err ~1.4e-7, R1-R14):
//   out[b][o][m] depends on b only through c = b & 7
//   three 1x1 convs fold into one 32x32 weight W + bias cb
//   slab[c][o][m] = cb[o] + sum_i W[o,i]  * v[256*((c+i)&7)+q, r]  (q=m/9, r=m%9)
//                         + sum_j W[o,9+j]* x[bb_j*43+20+(4j+m)%23],
//                           bb_j = (256c + (2304j+m)/23) & 2047
__global__ void __launch_bounds__(THREADS, 1) k_all(
    const float* __restrict__ x,
    const float* __restrict__ fc_w, const float* __restrict__ fc_b,
    const float* __restrict__ oh_w, const float* __restrict__ oh_b,
    const float* __restrict__ ot_w, const float* __restrict__ ot_b,
    const float* __restrict__ all_w, const float* __restrict__ all_b,
    float* __restrict__ out)
{
    __shared__ __align__(16) float s_fcw[EMB * SC];    // 7.2 KB
    __shared__ __align__(16) float s_W[OUTC * 32];     // fused weight
    __shared__ float s_cb[OUTC];                       // fused bias
    __shared__ float s_v[8][16][EMB];                  // embedding rows this tile needs
    __shared__ __align__(16) float s_out[OUTC * 128];  // 16 KB tile [o][m_local]

    const int t     = threadIdx.x;       // 0..1023
    const int mtile = blockIdx.x;        // 0..17
    const int c     = blockIdx.y;        // 0..7

    // ---- stage fc_w (coalesced) --------------------------------------------
    for (int i = t; i < EMB * SC; i += THREADS) s_fcw[i] = fc_w[i];

    // ---- fold the three convs into one 32x32 weight + bias (1 entry/thread)
    {
        int o = t >> 5, i = t & 31;
        float s = 0.f;
        if (i < EMB) {
            #pragma unroll
            for (int cc = 0; cc < EMB; cc++)
                s += all_w[o * 32 + cc] * oh_w[cc * EMB + i];
        } else {
            int j = i - EMB;
            #pragma unroll
            for (int cc = 0; cc < NOTH; cc++)
                s += all_w[o * 32 + EMB + cc] * ot_w[cc * NOTH + j];
        }
        s_W[t] = s;
    }
    if (t < OUTC) {
        float cb = all_b[t];
        #pragma unroll
        for (int cc = 0; cc < EMB; cc++)  cb += all_w[t * 32 + cc] * oh_b[cc];
        #pragma unroll
        for (int cc = 0; cc < NOTH; cc++) cb += all_w[t * 32 + EMB + cc] * ot_b[cc];
        s_cb[t] = cb;
    }
    __syncthreads();    // s_fcw ready

    // ---- embedding rows needed by this m-tile (<=128 rows, 1 per thread) ---
    const int m0 = mtile * 128;
    const int q0 = m0 / 9;
    const int nq = (m0 + 127) / 9 - q0 + 1;   // <= 16

    if (t < 8 * nq) {
        int k  = t / nq;
        int ql = t - k * nq;
        int b  = 256 * k + q0 + ql;
        const float* xr = x + b * XSTR;       // 20 consecutive floats (~3 lines)
        float acc[EMB];
        #pragma unroll
        for (int e = 0; e < EMB; e++) acc[e] = fc_b[e];
        #pragma unroll
        for (int j = 0; j < NOH; j++) {
            int id   = (int)xr[j];
            int base = j * NC + id;
            #pragma unroll
            for (int e = 0; e < EMB; e++) acc[e] += s_fcw[e * SC + base];
        }
        #pragma unroll
        for (int e = 0; e < EMB; e++) s_v[k][ql][e] = acc[e];
    }
    __syncthreads();    // s_W, s_cb, s_v ready

    // ---- compute tile: thread -> (m_local = t&127, 4 channels) -------------
    {
        const int ml = t & 127;
        const int o0 = (t >> 7) * 4;          // 8 groups of 4 channels
        const int m  = m0 + ml;
        const int q  = m / 9;
        const int r  = m - 9 * q;
        const int ql = q - q0;

        float g[32];
        #pragma unroll
        for (int i = 0; i < 9; i++)
            g[i] = s_v[(c + i) & 7][ql][r];
        #pragma unroll
        for (int j = 0; j < 23; j++) {
            int eo = (4 * j + m) % 23;
            int T  = (2304 * j + m) / 23;
            int bb = (256 * c + T) & 2047;
            g[9 + j] = x[bb * XSTR + NOH + eo];
        }

        #pragma unroll
        for (int chn = 0; chn < 4; chn++) {
            int o = o0 + chn;
            const float4* W4 = (const float4*)(s_W + o * 32);
            float s = s_cb[o];
            #pragma unroll
            for (int j4 = 0; j4 < 8; j4++) {
                float4 w = W4[j4];
                s += w.x * g[4 * j4]     + w.y * g[4 * j4 + 1]
                   + w.z * g[4 * j4 + 2] + w.w * g[4 * j4 + 3];
            }
            s_out[o * 128 + ml] = s;
        }
    }
    __syncthreads();    // tile ready (4096 floats = 1024 float4)

    // ---- store phase: each thread owns exactly ONE float4, streaming stores
    const float4 r0 = ((const float4*)s_out)[t];
    const int o   = t >> 5;
    const int ml4 = t & 31;

    float4* __restrict__ base = (float4*)out
        + (size_t)c * (SLABSZ / 4)            // batch residue component
        + (size_t)o * (HW / 4)                // channel
        + (size_t)(m0 >> 2) + ml4;            // spatial

    // stagger batch order per CTA to decorrelate chip-wide write windows
    const int cta   = mtile + 18 * c;         // 0..143
    const int start = (cta * 151) & 255;

    #pragma unroll 4
    for (int vv = 0; vv < 256; vv++) {
        int u = (vv + start) & 255;           // b = c + 8u
        __stcs(base + (size_t)u * (8 * SLABSZ / 4), r0);
    }
}

// ---------------------------------------------------------------------------
extern "C" void kernel_launch(void* const* d_in, const int* in_sizes, int n_in,
                              void* d_out, int out_size) {
    const float* x     = (const float*)d_in[0];
    const float* fc_w  = (const float*)d_in[1];
    const float* fc_b  = (const float*)d_in[2];
    const float* oh_w  = (const float*)d_in[3];
    const float* oh_b  = (const float*)d_in[4];
    const float* ot_w  = (const float*)d_in[5];
    const float* ot_b  = (const float*)d_in[6];
    const float* all_w = (const float*)d_in[7];
    const float* all_b = (const float*)d_in[8];
    float* out = (float*)d_out;

    dim3 grid(18, 8);   // 144 CTAs, single wave, 1 CTA/SM, 32 warps/SM
    k_all<<<grid, THREADS>>>(x, fc_w, fc_b, oh_w, oh_b, ot_w, ot_b,
                             all_w, all_b, out);
}